// round 9
// baseline (speedup 1.0000x reference)
#include <cuda_runtime.h>
#include <math.h>

#define BATCH 8
#define LL    128
#define NSPAN 1928
#define KSEL  10
#define BSK   (BATCH*NSPAN*KSEL)

// ---------------- device scratch (static: allowed) ----------------
__device__ int           g_lidx[NSPAN];
__device__ int           g_ridx[NSPAN];
__device__ int           g_geom[NSPAN * 8];
__device__ unsigned char g_cap[BATCH * NSPAN];
__device__ int           g_swap, g_wide;

__device__ __forceinline__ int span_base(int l) {
    return (l <= 113) ? (l << 4) : (NSPAN - (((128 - l) * (129 - l)) >> 1));
}

// ---------------- input classification (int32 vs int64 vs float) ----------------
__device__ __forceinline__ int classify(const unsigned* p) {
    bool allSmall = true, oddZero = true, anyNZ = false;
    for (int i = 0; i < 64; i++) {
        unsigned v = p[i];
        if (v >= 128u) allSmall = false;
        if ((i & 1) && v != 0u) oddZero = false;
        if (!(i & 1) && v != 0u) anyNZ = true;
    }
    if (!allSmall) return 0;
    return (oddZero && anyNZ) ? 2 : 1;
}
__global__ void k_detect(const unsigned* __restrict__ pA,
                         const unsigned* __restrict__ pB) {
    if (threadIdx.x != 0) return;
    int cA = classify(pA), cB = classify(pB);
    if      (cA > 0) { g_swap = 0; g_wide = (cA == 2); }
    else if (cB > 0) { g_swap = 1; g_wide = (cB == 2); }
    else             { g_swap = 0; g_wide = 0; }
}

// ---------------- spans + geom neighbor ids ----------------
__global__ void k_init() {
    int s = blockIdx.x * blockDim.x + threadIdx.x;
    if (s >= NSPAN) return;
    int l, r;
    if (s < 1808) { l = s >> 4; r = l + (s & 15); }
    else {
        l = 113;
        for (int c = 113; c < 127; c++) if (span_base(c + 1) <= s) l = c + 1;
        r = l + (s - span_base(l));
    }
    g_lidx[s] = l; g_ridx[s] = r;
    const int dl[8] = {-1,-1,-1, 0, 0, 1, 1, 1};
    const int dr[8] = {-1, 0, 1,-1, 1,-1, 0, 1};
    #pragma unroll
    for (int j = 0; j < 8; j++) {
        int nl = l + dl[j], nr = r + dr[j];
        int id = -1;
        if (nl >= 0 && nr >= nl && nr < LL && (nr - nl) <= 15)
            id = span_base(nl) + (nr - nl);
        g_geom[s * 8 + j] = id;
    }
}

// ---------------- raw idx read ----------------
__device__ __forceinline__ long long read_idx(const void* p, int wide, int off) {
    return wide ? ((const long long*)p)[off] : (long long)((const int*)p)[off];
}

// ---------------- CAP: first 128 spans (in t order) per top1 token ----------------
__global__ void k_cap(const void* __restrict__ inA, const void* __restrict__ inB) {
    __shared__ int sl[NSPAN], sr[NSPAN];
    int b = blockIdx.x, l = threadIdx.x;          // 128 threads = token ids
    for (int i = l; i < NSPAN; i += 128) { sl[i] = g_lidx[i]; sr[i] = g_ridx[i]; }
    __syncthreads();
    const void* pIdx = g_swap ? inB : inA;
    int wide = g_wide;
    int cnt = 0;
    for (int t = 0; t < NSPAN; t++) {
        int off = ((b * LL + sl[t]) * LL + sr[t]) * 4;
        long long raw = read_idx(pIdx, wide, off);
        int top1 = (raw >= 0) ? min((int)raw, LL - 1) : -1;
        if (top1 == l) { cnt++; g_cap[b * NSPAN + t] = (cnt <= 128) ? 1 : 0; }
        else if (top1 < 0 && l == 0) g_cap[b * NSPAN + t] = 0;
    }
}

// ---------------- prefill output (FLOAT contract) ----------------
__global__ void k_fill(float* __restrict__ out, int out_size) {
    int i = blockIdx.x * blockDim.x + threadIdx.x;
    if (i >= out_size) return;
    out[i] = (i < BSK) ? (float)((i / KSEL) % NSPAN) : 1.0f;
}

// ---------------- merge duplicates (k-order), sort ascending, pad ----------------
__device__ __forceinline__ int load_merge(const void* pIdx, const float* hw,
                                          int wide, int off,
                                          int* mi, float* mw, int* top1) {
    int ik[3]; float wk[3]; long long raw0 = -1;
    #pragma unroll
    for (int k = 0; k < 3; k++) {
        long long raw = read_idx(pIdx, wide, off + k);
        if (k == 0) raw0 = raw;
        bool v = (raw >= 0);
        ik[k] = v ? (int)raw : (1000 + k);
        wk[k] = v ? hw[off + k] : 0.0f;
    }
    *top1 = (raw0 >= 0) ? min((int)raw0, LL - 1) : -1;
    bool a1 = true, a2 = true;
    if (ik[1] == ik[0]) { wk[0] = __fadd_rn(wk[0], wk[1]); a1 = false; }
    if (ik[2] == ik[0]) { wk[0] = __fadd_rn(wk[0], wk[2]); a2 = false; }
    else if (a1 && ik[2] == ik[1]) { wk[1] = __fadd_rn(wk[1], wk[2]); a2 = false; }
    int cnt = 0;
    if (ik[0] < LL)       { mi[cnt] = ik[0]; mw[cnt] = wk[0]; cnt++; }
    if (a1 && ik[1] < LL) { mi[cnt] = ik[1]; mw[cnt] = wk[1]; cnt++; }
    if (a2 && ik[2] < LL) { mi[cnt] = ik[2]; mw[cnt] = wk[2]; cnt++; }
    if (cnt >= 2 && mi[0] > mi[1]) { int t = mi[0]; mi[0] = mi[1]; mi[1] = t;
                                     float f = mw[0]; mw[0] = mw[1]; mw[1] = f; }
    if (cnt == 3) {
        if (mi[1] > mi[2]) { int t = mi[1]; mi[1] = mi[2]; mi[2] = t;
                             float f = mw[1]; mw[1] = mw[2]; mw[2] = f; }
        if (mi[0] > mi[1]) { int t = mi[0]; mi[0] = mi[1]; mi[1] = t;
                             float f = mw[0]; mw[0] = mw[1]; mw[1] = f; }
    }
    #pragma unroll
    for (int k = 0; k < 3; k++) if (k >= cnt) { mi[k] = 0; mw[k] = 0.0f; }
    return cnt;
}

// ---------------- main: one block per (b,s), 128 threads ----------------
__global__ void __launch_bounds__(128)
k_bs(const void* __restrict__ inA, const void* __restrict__ inB,
     const float* __restrict__ dist, float* __restrict__ out) {
    __shared__ float    apw[LL];
    __shared__ unsigned sU[4];
    __shared__ unsigned sGeo[64];
    __shared__ float    smv[4 * KSEL];
    __shared__ int      smi[4 * KSEL];

    int s = blockIdx.x, b = blockIdx.y;
    int tid = threadIdx.x, lane = tid & 31, warp = tid >> 5;

    const void*  pIdx = g_swap ? inB : inA;
    const float* hw   = (const float*)(g_swap ? inA : inB);
    int wide = g_wide;
    const float* db = dist + b * LL * LL;

    // own span tokens (all threads redundantly -> registers)
    int l = g_lidx[s], r = g_ridx[s];
    int mi[3]; float mw[3]; int top1s;
    int cnt = load_merge(pIdx, hw, wide, ((b * LL + l) * LL + r) * 4, mi, mw, &top1s);

    // A_pw row + U bitmask (thread tid = token m)
    {
        int m = tid;
        float d0 = db[mi[0] * LL + m];
        float d1 = db[mi[1] * LL + m];
        float d2 = db[mi[2] * LL + m];
        float a = __fmaf_rn(mw[0], expf(-d0), 0.0f);
        a = __fmaf_rn(mw[1], expf(-d1), a);
        a = __fmaf_rn(mw[2], expf(-d2), a);
        apw[m] = a;
        bool bit = false;
        if (cnt > 0) bit |= (mi[0] == m) || (d0 <= 2.0f);
        if (cnt > 1) bit |= (mi[1] == m) || (d1 <= 2.0f);
        if (cnt > 2) bit |= (mi[2] == m) || (d2 <= 2.0f);
        unsigned bal = __ballot_sync(0xffffffffu, bit);
        if (lane == 0) sU[warp] = bal;
    }
    if (tid < 64) sGeo[tid] = 0u;
    __syncthreads();
    if (tid == 0) {
        #pragma unroll
        for (int j = 0; j < 8; j++) {
            int id = g_geom[s * 8 + j];
            if (id >= 0) sGeo[id >> 5] |= (1u << (id & 31));
        }
    }
    __syncthreads();

    // scan candidates t = tid, tid+128, ...
    float vv[KSEL]; int vi[KSEL];
    #pragma unroll
    for (int j = 0; j < KSEL; j++) { vv[j] = -INFINITY; vi[j] = s; }

    for (int t = tid; t < NSPAN; t += 128) {
        int lt = g_lidx[t], rt = g_ridx[t];
        int ci[3]; float cw[3]; int top1t;
        load_merge(pIdx, hw, wide, ((b * LL + lt) * LL + rt) * 4, ci, cw, &top1t);

        bool pass = (sGeo[t >> 5] >> (t & 31)) & 1u;
        if (!pass && top1t >= 0 && t != s && g_cap[b * NSPAN + t]) {
            pass = (sU[top1t >> 5] >> (top1t & 31)) & 1u;
        }
        if (!pass) continue;

        float g = __fmaf_rn(cw[0], apw[ci[0]], 0.0f);
        g = __fmaf_rn(cw[1], apw[ci[1]], g);
        g = __fmaf_rn(cw[2], apw[ci[2]], g);

        if (g > vv[KSEL - 1]) {
            vv[KSEL - 1] = g; vi[KSEL - 1] = t;
            #pragma unroll
            for (int j = KSEL - 2; j >= 0; j--) {
                if (vv[j + 1] > vv[j]) {
                    float tv = vv[j]; vv[j] = vv[j + 1]; vv[j + 1] = tv;
                    int   ti = vi[j]; vi[j] = vi[j + 1]; vi[j + 1] = ti;
                }
            }
        }
    }

    // butterfly merge within warp (tie -> smaller index)
    // CRITICAL: snapshot the partner's ENTIRE list via shuffles BEFORE any
    // mutation — both lanes mutate their lists during the merge, so inlined
    // shuffles would read partially-merged state (the R6/R8 bug).
    #pragma unroll
    for (int off = 16; off >= 1; off >>= 1) {
        float pv[KSEL]; int pi[KSEL];
        #pragma unroll
        for (int j = 0; j < KSEL; j++) {
            pv[j] = __shfl_xor_sync(0xffffffffu, vv[j], off);
            pi[j] = __shfl_xor_sync(0xffffffffu, vi[j], off);
        }
        #pragma unroll
        for (int j = 0; j < KSEL; j++) {
            float p = pv[j]; int q = pi[j];
            bool better = (p > vv[KSEL - 1]) ||
                          (p == vv[KSEL - 1] && p != -INFINITY && q < vi[KSEL - 1]);
            if (better) {
                vv[KSEL - 1] = p; vi[KSEL - 1] = q;
                #pragma unroll
                for (int k2 = KSEL - 2; k2 >= 0; k2--) {
                    bool sw = (vv[k2 + 1] > vv[k2]) ||
                              (vv[k2 + 1] == vv[k2] && vi[k2 + 1] < vi[k2]);
                    if (sw) {
                        float tv = vv[k2]; vv[k2] = vv[k2 + 1]; vv[k2 + 1] = tv;
                        int   ti = vi[k2]; vi[k2] = vi[k2 + 1]; vi[k2 + 1] = ti;
                    }
                }
            }
        }
    }

    if (lane == 0) {
        #pragma unroll
        for (int j = 0; j < KSEL; j++) { smv[warp * KSEL + j] = vv[j];
                                         smi[warp * KSEL + j] = vi[j]; }
    }
    __syncthreads();

    // thread 0: merge 4 warp lists (tie -> smaller index), write FLOAT indices
    if (tid == 0) {
        float fv[KSEL]; int fi[KSEL];
        #pragma unroll
        for (int j = 0; j < KSEL; j++) { fv[j] = -INFINITY; fi[j] = s; }
        for (int e = 0; e < 4 * KSEL; e++) {
            float p = smv[e]; int q = smi[e];
            if (p == -INFINITY) continue;
            bool better = (p > fv[KSEL - 1]) ||
                          (p == fv[KSEL - 1] && q < fi[KSEL - 1]);
            if (better) {
                fv[KSEL - 1] = p; fi[KSEL - 1] = q;
                #pragma unroll
                for (int k2 = KSEL - 2; k2 >= 0; k2--) {
                    bool sw = (fv[k2 + 1] > fv[k2]) ||
                              (fv[k2 + 1] == fv[k2] && fi[k2 + 1] < fi[k2]);
                    if (sw) {
                        float tv = fv[k2]; fv[k2] = fv[k2 + 1]; fv[k2 + 1] = tv;
                        int   ti = fi[k2]; fi[k2] = fi[k2 + 1]; fi[k2 + 1] = ti;
                    }
                }
            }
        }
        int base = (b * NSPAN + s) * KSEL;
        #pragma unroll
        for (int j = 0; j < KSEL; j++) out[base + j] = (float)fi[j];
    }
}

// ---------------- launch ----------------
extern "C" void kernel_launch(void* const* d_in, const int* in_sizes, int n_in,
                              void* d_out, int out_size) {
    const void* pA = d_in[0];
    const void* pB = d_in[1];
    const float* dist = (const float*)d_in[2];
    if (in_sizes[0] == BATCH * LL * LL)      { dist = (const float*)d_in[0]; pA = d_in[1]; pB = d_in[2]; }
    else if (in_sizes[1] == BATCH * LL * LL) { dist = (const float*)d_in[1]; pA = d_in[0]; pB = d_in[2]; }
    float* out = (float*)d_out;

    k_detect<<<1, 32>>>((const unsigned*)pA, (const unsigned*)pB);
    k_init<<<(NSPAN + 255) / 256, 256>>>();
    k_cap<<<BATCH, 128>>>(pA, pB);
    k_fill<<<(out_size + 255) / 256, 256>>>(out, out_size);

    dim3 grid(NSPAN, BATCH);
    k_bs<<<grid, 128>>>(pA, pB, dist, out);
}

// round 10
// speedup vs baseline: 4.6651x; 4.6651x over previous
#include <cuda_runtime.h>
#include <math.h>

#define BATCH 8
#define LL    128
#define NSPAN 1928
#define KSEL  10
#define WPB   16
#define BSK   (BATCH*NSPAN*KSEL)
#define NWORD 61   // ceil(1928/32)

// ---------------- device scratch (static: allowed) ----------------
__device__ int      g_lidx[NSPAN];
__device__ int      g_ridx[NSPAN];
__device__ unsigned g_lr  [NSPAN];            // l | r<<8
__device__ unsigned g_ptk [BATCH * NSPAN];    // byte0 top1(0xFF=excluded), b1-3 toks(0xFF=pad)
__device__ float    g_w0  [BATCH * NSPAN];
__device__ float    g_w1  [BATCH * NSPAN];
__device__ float    g_w2  [BATCH * NSPAN];
__device__ float    g_G   [BATCH * LL * LL];  // exp(-dist)
__device__ unsigned g_A   [BATCH * LL * 4];   // (dist<=2) bitmask rows
__device__ int      g_swap, g_wide;

__device__ __forceinline__ int span_base(int l) {
    return (l <= 113) ? (l << 4) : (NSPAN - (((128 - l) * (129 - l)) >> 1));
}

// ---------------- input classification (int32 vs int64 vs float) ----------------
__device__ __forceinline__ int classify(const unsigned* p) {
    bool allSmall = true, oddZero = true, anyNZ = false;
    for (int i = 0; i < 64; i++) {
        unsigned v = p[i];
        if (v >= 128u) allSmall = false;
        if ((i & 1) && v != 0u) oddZero = false;
        if (!(i & 1) && v != 0u) anyNZ = true;
    }
    if (!allSmall) return 0;
    return (oddZero && anyNZ) ? 2 : 1;
}
__global__ void k_detect(const unsigned* __restrict__ pA,
                         const unsigned* __restrict__ pB) {
    if (threadIdx.x != 0) return;
    int cA = classify(pA), cB = classify(pB);
    if      (cA > 0) { g_swap = 0; g_wide = (cA == 2); }
    else if (cB > 0) { g_swap = 1; g_wide = (cB == 2); }
    else             { g_swap = 0; g_wide = 0; }
}

// ---------------- spans ----------------
__global__ void k_init() {
    int s = blockIdx.x * blockDim.x + threadIdx.x;
    if (s >= NSPAN) return;
    int l, r;
    if (s < 1808) { l = s >> 4; r = l + (s & 15); }
    else {
        l = 113;
        for (int c = 113; c < 127; c++) if (span_base(c + 1) <= s) l = c + 1;
        r = l + (s - span_base(l));
    }
    g_lidx[s] = l; g_ridx[s] = r;
    g_lr[s] = (unsigned)l | ((unsigned)r << 8);
}

// ---------------- G = exp(-dist), A-bitmask ----------------
__global__ void k_exp(const float* __restrict__ dist) {
    int i = blockIdx.x * blockDim.x + threadIdx.x;   // BATCH*LL*LL threads
    float d = dist[i];
    g_G[i] = expf(-d);
    unsigned m = __ballot_sync(0xffffffffu, d <= 2.0f);
    if ((threadIdx.x & 31) == 0) g_A[i >> 5] = m;
}

// ---------------- raw idx read ----------------
__device__ __forceinline__ long long read_idx(const void* p, int wide, int off) {
    return wide ? ((const long long*)p)[off] : (long long)((const int*)p)[off];
}

// ---------------- token compaction (merge k-order, sort ascending, pad 0xFF/0.0) ----------------
__global__ void k_tok(const void* __restrict__ inA, const void* __restrict__ inB) {
    int gid = blockIdx.x * blockDim.x + threadIdx.x;
    if (gid >= BATCH * NSPAN) return;
    const void*  pIdx = g_swap ? inB : inA;
    const float* hw   = (const float*)(g_swap ? inA : inB);
    int wide = g_wide;

    int b = gid / NSPAN, s = gid - b * NSPAN;
    int off = ((b * LL + g_lidx[s]) * LL + g_ridx[s]) * 4;

    int ik[3]; float wk[3]; long long raw0 = -1;
    #pragma unroll
    for (int k = 0; k < 3; k++) {
        long long raw = read_idx(pIdx, wide, off + k);
        if (k == 0) raw0 = raw;
        bool v = (raw >= 0);
        ik[k] = v ? (int)raw : (1000 + k);
        wk[k] = v ? hw[off + k] : 0.0f;
    }
    unsigned top1 = (raw0 >= 0) ? (unsigned)min((int)raw0, LL - 1) : 0xFFu;

    bool a1 = true, a2 = true;
    if (ik[1] == ik[0]) { wk[0] = __fadd_rn(wk[0], wk[1]); a1 = false; }
    if (ik[2] == ik[0]) { wk[0] = __fadd_rn(wk[0], wk[2]); a2 = false; }
    else if (a1 && ik[2] == ik[1]) { wk[1] = __fadd_rn(wk[1], wk[2]); a2 = false; }

    int mi[3] = {255, 255, 255}; float mw[3] = {0.f, 0.f, 0.f}; int cnt = 0;
    if (ik[0] < LL)       { mi[cnt] = ik[0]; mw[cnt] = wk[0]; cnt++; }
    if (a1 && ik[1] < LL) { mi[cnt] = ik[1]; mw[cnt] = wk[1]; cnt++; }
    if (a2 && ik[2] < LL) { mi[cnt] = ik[2]; mw[cnt] = wk[2]; cnt++; }

    if (cnt >= 2 && mi[0] > mi[1]) { int t = mi[0]; mi[0] = mi[1]; mi[1] = t;
                                     float f = mw[0]; mw[0] = mw[1]; mw[1] = f; }
    if (cnt == 3) {
        if (mi[1] > mi[2]) { int t = mi[1]; mi[1] = mi[2]; mi[2] = t;
                             float f = mw[1]; mw[1] = mw[2]; mw[2] = f; }
        if (mi[0] > mi[1]) { int t = mi[0]; mi[0] = mi[1]; mi[1] = t;
                             float f = mw[0]; mw[0] = mw[1]; mw[1] = f; }
    }
    g_ptk[gid] = top1 | ((unsigned)mi[0] << 8) | ((unsigned)mi[1] << 16)
               | ((unsigned)mi[2] << 24);
    g_w0[gid] = mw[0]; g_w1[gid] = mw[1]; g_w2[gid] = mw[2];
}

// ---------------- CAP folded into top1 byte (smem-staged scan) ----------------
__global__ void k_cap() {
    __shared__ unsigned sp[NSPAN];
    int b = blockIdx.x, l = threadIdx.x;          // 128 threads = token ids
    for (int i = l; i < NSPAN; i += 128) sp[i] = g_ptk[b * NSPAN + i];
    __syncthreads();
    int cnt = 0;
    for (int t = 0; t < NSPAN; t++) {
        if ((sp[t] & 0xFFu) == (unsigned)l) {
            cnt++;
            if (cnt > 128) sp[t] |= 0xFFu;        // exclude from U path
        }
    }
    __syncthreads();
    for (int i = l; i < NSPAN; i += 128) g_ptk[b * NSPAN + i] = sp[i];
}

// ---------------- prefill output (FLOAT contract) ----------------
__global__ void k_fill(float* __restrict__ out, int out_size) {
    int i = blockIdx.x * blockDim.x + threadIdx.x;
    if (i >= out_size) return;
    out[i] = (i < BSK) ? (float)((i / KSEL) % NSPAN) : 1.0f;
}

// ---------------- main: 1 warp per span, candidate table in smem ----------------
__global__ void __launch_bounds__(WPB * 32, 1)
k_main(float* __restrict__ out) {
    __shared__ unsigned sPtk[NSPAN];              //  7712 B
    __shared__ float    sW0[NSPAN];               //  7712 B
    __shared__ float    sW1[NSPAN];               //  7712 B
    __shared__ float    sW2[NSPAN];               //  7712 B
    __shared__ unsigned sLR[NSPAN];               //  7712 B  (l | r<<8)
    __shared__ float    sApw[WPB][LL];            //  8192 B
    __shared__ unsigned sU[WPB][8];               //   512 B  (256-bit: hi 128 zero)

    int b = blockIdx.y;
    int tid = threadIdx.x, lane = tid & 31, warp = tid >> 5;
    int base = b * NSPAN;

    for (int i = tid; i < NSPAN; i += WPB * 32) {
        sPtk[i] = g_ptk[base + i];
        sW0[i]  = g_w0[base + i];
        sW1[i]  = g_w1[base + i];
        sW2[i]  = g_w2[base + i];
        sLR[i]  = g_lr[i];
    }
    __syncthreads();

    int s = blockIdx.x * WPB + warp;
    if (s >= NSPAN) return;

    unsigned ptk_s = sPtk[s];
    int t0 = (ptk_s >>  8) & 0xFF;
    int t1 = (ptk_s >> 16) & 0xFF;
    int t2 = (ptk_s >> 24) & 0xFF;
    float w0 = sW0[s], w1 = sW1[s], w2 = sW2[s];
    const float*    Gb = g_G + b * LL * LL;
    const unsigned* Ab = g_A + b * LL * 4;

    // per-warp U bitmask + A_pw row (identical FFMA chain to the passing R9)
    #pragma unroll
    for (int q = 0; q < 4; q++) {
        int m = q * 32 + lane;
        bool bit = false;
        if (t0 < LL) bit |= (t0 == m) || ((Ab[t0 * 4 + q] >> lane) & 1u);
        if (t1 < LL) bit |= (t1 == m) || ((Ab[t1 * 4 + q] >> lane) & 1u);
        if (t2 < LL) bit |= (t2 == m) || ((Ab[t2 * 4 + q] >> lane) & 1u);
        unsigned bal = __ballot_sync(0xffffffffu, bit);
        if (lane == 0) { sU[warp][q] = bal; sU[warp][q + 4] = 0u; }
        float a = __fmaf_rn(w0, Gb[(t0 & 0x7F) * LL + m], 0.0f);
        a = __fmaf_rn(w1, Gb[(t1 & 0x7F) * LL + m], a);
        a = __fmaf_rn(w2, Gb[(t2 & 0x7F) * LL + m], a);
        sApw[warp][m] = a;
    }
    __syncwarp();

    unsigned lr_s = sLR[s];
    int ls = lr_s & 0xFF, rs = (lr_s >> 8) & 0xFF;

    float vv[KSEL]; int vi[KSEL];
    #pragma unroll
    for (int j = 0; j < KSEL; j++) { vv[j] = -INFINITY; vi[j] = s; }
    const float* apw = sApw[warp];

    for (int t = lane; t < NSPAN; t += 32) {
        unsigned ptk = sPtk[t];
        unsigned byte = ptk & 0xFFu;
        unsigned ub = (sU[warp][byte >> 5] >> (byte & 31)) & 1u;   // 0 if byte>=128
        unsigned lr = sLR[t];
        int lt = lr & 0xFF, rt = (lr >> 8) & 0xFF;
        int dlr = abs(lt - ls) | abs(rt - rs);
        bool gb = (dlr <= 1) && (t != s);
        bool pass = (ub && t != s) || gb;
        if (!pass) continue;

        float g = __fmaf_rn(sW0[t], apw[(ptk >>  8) & 0x7F], 0.0f);
        g = __fmaf_rn(sW1[t], apw[(ptk >> 16) & 0x7F], g);
        g = __fmaf_rn(sW2[t], apw[(ptk >> 24) & 0x7F], g);

        if (g > vv[KSEL - 1]) {
            vv[KSEL - 1] = g; vi[KSEL - 1] = t;
            #pragma unroll
            for (int j = KSEL - 2; j >= 0; j--) {
                if (vv[j + 1] > vv[j]) {
                    float tv = vv[j]; vv[j] = vv[j + 1]; vv[j + 1] = tv;
                    int   ti = vi[j]; vi[j] = vi[j + 1]; vi[j + 1] = ti;
                }
            }
        }
    }

    // butterfly merge: snapshot partner's FULL list before mutating (R9 fix)
    #pragma unroll
    for (int off = 16; off >= 1; off >>= 1) {
        float pv[KSEL]; int pi[KSEL];
        #pragma unroll
        for (int j = 0; j < KSEL; j++) {
            pv[j] = __shfl_xor_sync(0xffffffffu, vv[j], off);
            pi[j] = __shfl_xor_sync(0xffffffffu, vi[j], off);
        }
        #pragma unroll
        for (int j = 0; j < KSEL; j++) {
            float p = pv[j]; int q = pi[j];
            bool better = (p > vv[KSEL - 1]) ||
                          (p == vv[KSEL - 1] && p != -INFINITY && q < vi[KSEL - 1]);
            if (better) {
                vv[KSEL - 1] = p; vi[KSEL - 1] = q;
                #pragma unroll
                for (int k2 = KSEL - 2; k2 >= 0; k2--) {
                    bool sw = (vv[k2 + 1] > vv[k2]) ||
                              (vv[k2 + 1] == vv[k2] && vi[k2 + 1] < vi[k2]);
                    if (sw) {
                        float tv = vv[k2]; vv[k2] = vv[k2 + 1]; vv[k2 + 1] = tv;
                        int   ti = vi[k2]; vi[k2] = vi[k2 + 1]; vi[k2 + 1] = ti;
                    }
                }
            }
        }
    }

    if (lane == 0) {
        int ob = (base + s) * KSEL;
        #pragma unroll
        for (int j = 0; j < KSEL; j++) out[ob + j] = (float)vi[j];
    }
}

// ---------------- launch ----------------
extern "C" void kernel_launch(void* const* d_in, const int* in_sizes, int n_in,
                              void* d_out, int out_size) {
    const void* pA = d_in[0];
    const void* pB = d_in[1];
    const float* dist = (const float*)d_in[2];
    if (in_sizes[0] == BATCH * LL * LL)      { dist = (const float*)d_in[0]; pA = d_in[1]; pB = d_in[2]; }
    else if (in_sizes[1] == BATCH * LL * LL) { dist = (const float*)d_in[1]; pA = d_in[0]; pB = d_in[2]; }
    float* out = (float*)d_out;

    k_detect<<<1, 32>>>((const unsigned*)pA, (const unsigned*)pB);
    k_init<<<(NSPAN + 255) / 256, 256>>>();
    k_exp<<<(BATCH * LL * LL) / 256, 256>>>(dist);
    k_tok<<<(BATCH * NSPAN + 255) / 256, 256>>>(pA, pB);
    k_cap<<<BATCH, 128>>>();
    k_fill<<<(out_size + 255) / 256, 256>>>(out, out_size);

    dim3 grid((NSPAN + WPB - 1) / WPB, BATCH);
    k_main<<<grid, WPB * 32>>>(out);
}